// round 2
// baseline (speedup 1.0000x reference)
#include <cuda_runtime.h>
#include <math.h>

#define D        64
#define MQ       32      // queries per block
#define TK       64      // key tile
#define TOPK     32
#define THREADS  256
#define NEG_INF  (-3.402823466e38f)

struct __align__(16) SmemLayout {
    float Qs[D][MQ + 1];        // transposed, pre-scaled q  [d][q]
    float Ks[TK][D + 1];        // k tile                    [l][d]
    float Vs[TK][D];            // v tile                    [l][d]
    float Ss[MQ][TK + 4];       // score tile / final sums   [q][l]
    float tsc[MQ][TOPK + 1];    // top-k scores
    int   tix[MQ][TOPK + 1];    // top-k indices
    float cnt[MQ];
    unsigned char Ms[TK][MQ];   // mask tile [l][q]
};

__global__ __launch_bounds__(THREADS)
void ga_kernel(const float* __restrict__ q, const float* __restrict__ k,
               const float* __restrict__ v, const int* __restrict__ mask,
               float* __restrict__ out, int B, int Lq, int L)
{
    extern __shared__ unsigned char smem_raw[];
    SmemLayout* S = reinterpret_cast<SmemLayout*>(smem_raw);

    const int tid = threadIdx.x;
    const int b   = blockIdx.y;
    const int q0g = blockIdx.x * MQ;         // first query (within batch)

    const int qa = 2 * (tid >> 4);           // this thread's query pair: qa, qa+1
    const int kc = 4 * (tid & 15);           // this thread's key/dim quad

    // ---- load Q tile, transposed + pre-scaled ----
    {
        const float scale = 1.0f / sqrtf((float)D);
        for (int j = tid; j < MQ * D; j += THREADS) {
            int qi = j >> 6, d = j & 63;
            S->Qs[d][qi] = q[((size_t)b * Lq + q0g + qi) * D + d] * scale;
        }
    }
    // ---- init top-k buffers ----
    for (int j = tid; j < MQ * TOPK; j += THREADS) {
        S->tsc[j / TOPK][j % TOPK] = NEG_INF;
        S->tix[j / TOPK][j % TOPK] = -1;
    }

    float acc_sum[8];                        // mask*V accumulators: 2q x 4d
    #pragma unroll
    for (int i = 0; i < 8; i++) acc_sum[i] = 0.0f;

    // merge-thread state (tid < MQ owns query tid)
    float thr = NEG_INF;
    int   minpos = 0;
    float mycnt = 0.0f;

    const size_t kbase = (size_t)b * L * D;

    for (int l0 = 0; l0 < L; l0 += TK) {
        // ---- load K and V tiles (coalesced float4 global reads) ----
        #pragma unroll
        for (int r = 0; r < (TK * D / 4) / THREADS; r++) {   // 4 iters
            int idx4 = tid + THREADS * r;
            int i  = idx4 >> 4;
            int c4 = (idx4 & 15) << 2;
            const float4 tk = *(const float4*)(k + kbase + (size_t)(l0 + i) * D + c4);
            S->Ks[i][c4 + 0] = tk.x; S->Ks[i][c4 + 1] = tk.y;
            S->Ks[i][c4 + 2] = tk.z; S->Ks[i][c4 + 3] = tk.w;
            const float4 tv = *(const float4*)(v + kbase + (size_t)(l0 + i) * D + c4);
            *(float4*)&S->Vs[i][c4] = tv;
        }
        // ---- load mask tile (int32 in gmem): 64 l x 32 q -> byte tile ----
        {
            int qi = tid >> 3, c8 = (tid & 7) << 3;
            const int4* mp = (const int4*)(mask + (size_t)(b * Lq + q0g + qi) * L + l0 + c8);
            int4 m0 = mp[0];
            int4 m1 = mp[1];
            S->Ms[c8 + 0][qi] = (unsigned char)(m0.x != 0);
            S->Ms[c8 + 1][qi] = (unsigned char)(m0.y != 0);
            S->Ms[c8 + 2][qi] = (unsigned char)(m0.z != 0);
            S->Ms[c8 + 3][qi] = (unsigned char)(m0.w != 0);
            S->Ms[c8 + 4][qi] = (unsigned char)(m1.x != 0);
            S->Ms[c8 + 5][qi] = (unsigned char)(m1.y != 0);
            S->Ms[c8 + 6][qi] = (unsigned char)(m1.z != 0);
            S->Ms[c8 + 7][qi] = (unsigned char)(m1.w != 0);
        }
        __syncthreads();

        // ---- scores: 2q x 4k micro-tile ----
        float sc[8];
        #pragma unroll
        for (int i = 0; i < 8; i++) sc[i] = 0.0f;
        #pragma unroll 4
        for (int d = 0; d < D; d++) {
            float a0 = S->Qs[d][qa];
            float a1 = S->Qs[d][qa + 1];
            float b0 = S->Ks[kc + 0][d];
            float b1 = S->Ks[kc + 1][d];
            float b2 = S->Ks[kc + 2][d];
            float b3 = S->Ks[kc + 3][d];
            sc[0] = fmaf(a0, b0, sc[0]); sc[1] = fmaf(a0, b1, sc[1]);
            sc[2] = fmaf(a0, b2, sc[2]); sc[3] = fmaf(a0, b3, sc[3]);
            sc[4] = fmaf(a1, b0, sc[4]); sc[5] = fmaf(a1, b1, sc[5]);
            sc[6] = fmaf(a1, b2, sc[6]); sc[7] = fmaf(a1, b3, sc[7]);
        }
        *(float4*)&S->Ss[qa][kc]     = make_float4(sc[0], sc[1], sc[2], sc[3]);
        *(float4*)&S->Ss[qa + 1][kc] = make_float4(sc[4], sc[5], sc[6], sc[7]);

        // ---- mask * V accumulation: 2q x 4d micro-tile ----
        #pragma unroll 4
        for (int l = 0; l < TK; l++) {
            float m0 = S->Ms[l][qa]     ? 1.0f : 0.0f;
            float m1 = S->Ms[l][qa + 1] ? 1.0f : 0.0f;
            float4 v4 = *(const float4*)&S->Vs[l][kc];
            acc_sum[0] = fmaf(m0, v4.x, acc_sum[0]);
            acc_sum[1] = fmaf(m0, v4.y, acc_sum[1]);
            acc_sum[2] = fmaf(m0, v4.z, acc_sum[2]);
            acc_sum[3] = fmaf(m0, v4.w, acc_sum[3]);
            acc_sum[4] = fmaf(m1, v4.x, acc_sum[4]);
            acc_sum[5] = fmaf(m1, v4.y, acc_sum[5]);
            acc_sum[6] = fmaf(m1, v4.z, acc_sum[6]);
            acc_sum[7] = fmaf(m1, v4.w, acc_sum[7]);
        }
        __syncthreads();

        // ---- top-k merge: thread tid < MQ owns query tid ----
        if (tid < MQ) {
            #pragma unroll 1
            for (int kk = 0; kk < TK; kk++) {
                if (S->Ms[kk][tid]) {
                    mycnt += 1.0f;
                    float s = S->Ss[tid][kk];
                    if (s > thr) {
                        S->tsc[tid][minpos] = s;
                        S->tix[tid][minpos] = l0 + kk;
                        float nm = S->tsc[tid][0]; int np = 0;
                        #pragma unroll
                        for (int i = 1; i < TOPK; i++) {
                            float ti = S->tsc[tid][i];
                            if (ti < nm) { nm = ti; np = i; }
                        }
                        thr = nm; minpos = np;
                    }
                }
            }
        }
        __syncthreads();
    }

    // ---- dump mask*V sums into Ss (reused as [q][d] sums) ----
    *(float4*)&S->Ss[qa][kc]     = make_float4(acc_sum[0], acc_sum[1], acc_sum[2], acc_sum[3]);
    *(float4*)&S->Ss[qa + 1][kc] = make_float4(acc_sum[4], acc_sum[5], acc_sum[6], acc_sum[7]);
    if (tid < MQ) S->cnt[tid] = mycnt;
    __syncthreads();

    // ---- epilogue: softmax over top-32, gather V, add mean ----
    const int wid  = tid >> 5;
    const int lane = tid & 31;
    const float* vb = v + kbase;
    for (int qq = wid; qq < MQ; qq += (THREADS / 32)) {
        float s  = S->tsc[qq][lane];
        int   ix = S->tix[qq][lane];
        bool valid = (ix >= 0);
        float sv = valid ? s : NEG_INF;
        float m = sv;
        #pragma unroll
        for (int off = 16; off > 0; off >>= 1)
            m = fmaxf(m, __shfl_xor_sync(0xFFFFFFFFu, m, off));
        float e = valid ? expf(s - m) : 0.0f;
        float den = e;
        #pragma unroll
        for (int off = 16; off > 0; off >>= 1)
            den += __shfl_xor_sync(0xFFFFFFFFu, den, off);
        float w = (den > 0.0f) ? (e / den) : 0.0f;

        float a0 = 0.0f, a1 = 0.0f;
        #pragma unroll 1
        for (int i = 0; i < TOPK; i++) {
            float wi = __shfl_sync(0xFFFFFFFFu, w, i);
            int   ii = __shfl_sync(0xFFFFFFFFu, ix, i);
            if (ii >= 0) {
                const float* vr = vb + (size_t)ii * D;
                a0 = fmaf(wi, vr[lane],      a0);
                a1 = fmaf(wi, vr[lane + 32], a1);
            }
        }
        float c = fmaxf(S->cnt[qq], 1.0f);
        size_t obase = ((size_t)(b * Lq + q0g + qq)) * D;
        out[obase + lane]      = S->Ss[qq][lane]      / c + a0;
        out[obase + lane + 32] = S->Ss[qq][lane + 32] / c + a1;
    }
}

extern "C" void kernel_launch(void* const* d_in, const int* in_sizes, int n_in,
                              void* d_out, int out_size)
{
    const float* q = (const float*)d_in[0];
    const float* k = (const float*)d_in[1];
    const float* v = (const float*)d_in[2];
    const int*   mask = (const int*)d_in[3];
    float* out = (float*)d_out;

    int N     = in_sizes[0] / D;   // B * Lq
    int Ktot  = in_sizes[1] / D;   // B * L
    int L     = in_sizes[3] / N;
    int B     = Ktot / L;
    int Lq    = N / B;

    int smem = (int)sizeof(SmemLayout);
    cudaFuncSetAttribute(ga_kernel, cudaFuncAttributeMaxDynamicSharedMemorySize, smem);

    dim3 grid(Lq / MQ, B);
    ga_kernel<<<grid, THREADS, smem>>>(q, k, v, mask, out, B, Lq, L);
}

// round 3
// speedup vs baseline: 2.3146x; 2.3146x over previous
#include <cuda_runtime.h>
#include <math.h>

#define D        64
#define MQ       32      // queries per block
#define TK       64      // key tile (one u64 bitmask)
#define TOPK     32
#define THREADS  256
#define NEG_INF  (-3.402823466e38f)

typedef unsigned long long u64;

struct __align__(16) SmemLayout {
    float  Qs[MQ][D + 4];       // [q][d] pre-scaled, stride 68
    float  Ks[TK][D + 4];       // [l][d] stride 68
    float  Vs[TK][D];           // [l][d] stride 64
    float  Ss[MQ][D + 4];       // scores [q][k] / final sums [q][d]
    float2 Msd[TK][MQ + 1];     // duplicated mask floats (m,m) per [l][q]
    float  tsc[MQ][TOPK];       // top-k scores
    int    tix[MQ][TOPK];       // top-k indices
    u64    Mbits[MQ];           // mask bits of current tile
    u64    cand[MQ];            // candidate bits of current tile
    float  thr[MQ];             // current heap-min per query
    float  cnt[MQ];
};

__device__ __forceinline__ void fma2(u64& d, u64 a, u64 b) {
    asm("fma.rn.f32x2 %0, %1, %2, %0;" : "+l"(d) : "l"(a), "l"(b));
}
__device__ __forceinline__ float2 unpack2(u64 a) {
    float2 r;
    asm("mov.b64 {%0,%1}, %2;" : "=f"(r.x), "=f"(r.y) : "l"(a));
    return r;
}

__global__ __launch_bounds__(THREADS)
void ga_kernel(const float* __restrict__ q, const float* __restrict__ k,
               const float* __restrict__ v, const int* __restrict__ mask,
               float* __restrict__ out, int B, int Lq, int L)
{
    extern __shared__ unsigned char smem_raw[];
    SmemLayout* S = reinterpret_cast<SmemLayout*>(smem_raw);

    const int tid = threadIdx.x;
    const int b   = blockIdx.y;
    const int q0g = blockIdx.x * MQ;

    const int t15 = tid & 15;
    const int qa  = 2 * (tid >> 4);      // thread's query pair
    const int dc  = 4 * t15;             // mask*V: d quad

    // ---- init: Q tile (pre-scaled), top-k buffers, per-query state ----
    {
        const float scale = 1.0f / sqrtf((float)D);
        for (int j = tid; j < MQ * D; j += THREADS) {
            int qi = j >> 6, d = j & 63;
            S->Qs[qi][d] = q[((size_t)b * Lq + q0g + qi) * D + d] * scale;
        }
    }
    for (int j = tid; j < MQ * TOPK; j += THREADS) {
        S->tsc[j / TOPK][j % TOPK] = NEG_INF;
        S->tix[j / TOPK][j % TOPK] = -1;
    }
    if (tid < MQ) {
        S->thr[tid]   = NEG_INF;
        S->Mbits[tid] = 0ull;
        S->cand[tid]  = 0ull;
    }

    // persistent mask*V accumulators: 2q x 4d as 4 f32x2 pairs
    u64 mv00 = 0ull, mv01 = 0ull, mv10 = 0ull, mv11 = 0ull;

    // merge-thread state (tid < MQ owns query tid)
    float thrL = NEG_INF;
    int   minpos = 0;
    float cntL = 0.0f;

    const size_t kbase = (size_t)b * L * D;

    for (int l0 = 0; l0 < L; l0 += TK) {
        // ================= phase 1: load tile =================
        #pragma unroll
        for (int r = 0; r < (TK * D / 4) / THREADS; r++) {   // 4 iters
            int idx4 = tid + THREADS * r;
            int i  = idx4 >> 4;
            int c4 = (idx4 & 15) << 2;
            const float4 tk = *(const float4*)(k + kbase + (size_t)(l0 + i) * D + c4);
            *(float4*)&S->Ks[i][c4] = tk;
            const float4 tv = *(const float4*)(v + kbase + (size_t)(l0 + i) * D + c4);
            *(float4*)&S->Vs[i][c4] = tv;
        }
        {   // mask: 8 int32 per thread -> bits + duplicated floats
            int qi = tid >> 3, c8 = (tid & 7) << 3;
            const int4* mp = (const int4*)(mask + (size_t)(b * Lq + q0g + qi) * L + l0 + c8);
            int4 m0 = mp[0];
            int4 m1 = mp[1];
            int mm[8] = { m0.x, m0.y, m0.z, m0.w, m1.x, m1.y, m1.z, m1.w };
            u64 bits = 0ull;
            #pragma unroll
            for (int jj = 0; jj < 8; jj++) {
                int on = (mm[jj] != 0);
                bits |= (u64)on << (c8 + jj);
                float mf = (float)on;
                S->Msd[c8 + jj][qi] = make_float2(mf, mf);
            }
            if (bits) atomicOr(&S->Mbits[qi], bits);
        }
        __syncthreads();

        // ================= phase 2: compute =================
        const float thr0 = S->thr[qa];
        const float thr1 = S->thr[qa + 1];
        const u64   Mb0  = S->Mbits[qa];
        const u64   Mb1  = S->Mbits[qa + 1];

        // ---- scores: 2q x 4k (k rows t15 + 16j), f32x2 pairwise over d ----
        u64 sp[2][4];
        #pragma unroll
        for (int qi = 0; qi < 2; qi++)
            #pragma unroll
            for (int j = 0; j < 4; j++) sp[qi][j] = 0ull;

        #pragma unroll 4
        for (int d = 0; d < D; d += 4) {
            ulonglong2 Q0 = *(const ulonglong2*)&S->Qs[qa][d];
            ulonglong2 Q1 = *(const ulonglong2*)&S->Qs[qa + 1][d];
            #pragma unroll
            for (int j = 0; j < 4; j++) {
                ulonglong2 Kj = *(const ulonglong2*)&S->Ks[t15 + 16 * j][d];
                fma2(sp[0][j], Q0.x, Kj.x);
                fma2(sp[0][j], Q0.y, Kj.y);
                fma2(sp[1][j], Q1.x, Kj.x);
                fma2(sp[1][j], Q1.y, Kj.y);
            }
        }
        // finalize scores, candidate bits
        u64 w0 = 0ull, w1 = 0ull;
        #pragma unroll
        for (int j = 0; j < 4; j++) {
            int kpos = t15 + 16 * j;
            float2 p0 = unpack2(sp[0][j]);
            float  s0 = p0.x + p0.y;
            S->Ss[qa][kpos] = s0;
            if (s0 > thr0 && ((Mb0 >> kpos) & 1ull)) w0 |= 1ull << kpos;
            float2 p1 = unpack2(sp[1][j]);
            float  s1 = p1.x + p1.y;
            S->Ss[qa + 1][kpos] = s1;
            if (s1 > thr1 && ((Mb1 >> kpos) & 1ull)) w1 |= 1ull << kpos;
        }
        if (w0) atomicOr(&S->cand[qa], w0);
        if (w1) atomicOr(&S->cand[qa + 1], w1);

        // ---- mask*V: 2q x 4d, packed over d ----
        #pragma unroll 4
        for (int l = 0; l < TK; l++) {
            ulonglong2 v2 = *(const ulonglong2*)&S->Vs[l][dc];
            u64 m0 = *(const u64*)&S->Msd[l][qa];
            u64 m1 = *(const u64*)&S->Msd[l][qa + 1];
            fma2(mv00, m0, v2.x);
            fma2(mv01, m0, v2.y);
            fma2(mv10, m1, v2.x);
            fma2(mv11, m1, v2.y);
        }
        __syncthreads();

        // ================= phase 3: merge candidates =================
        if (tid < MQ) {
            const int qq = tid;
            u64 w = S->cand[qq];
            cntL += (float)__popcll(S->Mbits[qq]);
            while (w) {
                int kk = __ffsll((long long)w) - 1;
                w &= w - 1ull;
                float s = S->Ss[qq][kk];
                if (s > thrL) {
                    S->tsc[qq][minpos] = s;
                    S->tix[qq][minpos] = l0 + kk;
                    float nm = S->tsc[qq][0]; int np = 0;
                    #pragma unroll
                    for (int i = 1; i < TOPK; i++) {
                        float ti = S->tsc[qq][i];
                        if (ti < nm) { nm = ti; np = i; }
                    }
                    thrL = nm; minpos = np;
                }
            }
            S->thr[qq]   = thrL;
            S->Mbits[qq] = 0ull;
            S->cand[qq]  = 0ull;
        }
        __syncthreads();
    }

    // ---- dump mask*V sums into Ss (reused as [q][d]) ----
    {
        float2 a = unpack2(mv00), bq = unpack2(mv01);
        *(float4*)&S->Ss[qa][dc] = make_float4(a.x, a.y, bq.x, bq.y);
        float2 c = unpack2(mv10), dq = unpack2(mv11);
        *(float4*)&S->Ss[qa + 1][dc] = make_float4(c.x, c.y, dq.x, dq.y);
    }
    if (tid < MQ) S->cnt[tid] = cntL;
    __syncthreads();

    // ---- epilogue: softmax over top-32, gather V, add mean ----
    const int wid  = tid >> 5;
    const int lane = tid & 31;
    const float* vb = v + kbase;
    for (int qq = wid; qq < MQ; qq += (THREADS / 32)) {
        float s  = S->tsc[qq][lane];
        int   ix = S->tix[qq][lane];
        bool valid = (ix >= 0);
        float sv = valid ? s : NEG_INF;
        float m = sv;
        #pragma unroll
        for (int off = 16; off > 0; off >>= 1)
            m = fmaxf(m, __shfl_xor_sync(0xFFFFFFFFu, m, off));
        float e = valid ? expf(s - m) : 0.0f;
        float den = e;
        #pragma unroll
        for (int off = 16; off > 0; off >>= 1)
            den += __shfl_xor_sync(0xFFFFFFFFu, den, off);
        float w = (den > 0.0f) ? (e / den) : 0.0f;

        float a0 = 0.0f, a1 = 0.0f;
        #pragma unroll 1
        for (int i = 0; i < TOPK; i++) {
            float wi = __shfl_sync(0xFFFFFFFFu, w, i);
            int   ii = __shfl_sync(0xFFFFFFFFu, ix, i);
            if (ii >= 0) {
                const float* vr = vb + (size_t)ii * D;
                a0 = fmaf(wi, vr[lane],      a0);
                a1 = fmaf(wi, vr[lane + 32], a1);
            }
        }
        float c = fmaxf(S->cnt[qq], 1.0f);
        size_t obase = ((size_t)(b * Lq + q0g + qq)) * D;
        out[obase + lane]      = S->Ss[qq][lane]      / c + a0;
        out[obase + lane + 32] = S->Ss[qq][lane + 32] / c + a1;
    }
}

extern "C" void kernel_launch(void* const* d_in, const int* in_sizes, int n_in,
                              void* d_out, int out_size)
{
    const float* q = (const float*)d_in[0];
    const float* k = (const float*)d_in[1];
    const float* v = (const float*)d_in[2];
    const int*   mask = (const int*)d_in[3];
    float* out = (float*)d_out;

    int N     = in_sizes[0] / D;   // B * Lq
    int Ktot  = in_sizes[1] / D;   // B * L
    int L     = in_sizes[3] / N;
    int B     = Ktot / L;
    int Lq    = N / B;

    int smem = (int)sizeof(SmemLayout);
    cudaFuncSetAttribute(ga_kernel, cudaFuncAttributeMaxDynamicSharedMemorySize, smem);

    dim3 grid(Lq / MQ, B);
    ga_kernel<<<grid, THREADS, smem>>>(q, k, v, mask, out, B, Lq, L);
}